// round 10
// baseline (speedup 1.0000x reference)
#include <cuda_runtime.h>
#include <cstdint>

#define GRID   444
#define BLOCK  256
#define NE     8
#define HDIM   1024

__device__ float g_partials[GRID * 16];
__device__ int   g_ticket = 0;

// Packed fp32x2 FMA (Blackwell): d.lo += a.lo*b.lo ; d.hi += a.hi*b.hi
#define FMA2(d, a, b) asm("fma.rn.f32x2 %0, %1, %2, %0;" : "+l"(d) : "l"(a), "l"(b))

__device__ __forceinline__ void suffix_scan256(int* h, int n)
{
    // inclusive suffix sums, n <= 2048, 256 threads
    for (int off = 1; off < n; off <<= 1) {
        int v[8]; int c = 0;
        for (int i = threadIdx.x; i < n; i += BLOCK) {
            const int add = (i + off < n) ? h[i + off] : 0;
            v[c++] = h[i] + add;
        }
        __syncthreads();
        c = 0;
        for (int i = threadIdx.x; i < n; i += BLOCK) h[i] = v[c++];
        __syncthreads();
    }
}

__global__ void __launch_bounds__(BLOCK, 3)
route_fused(const float* __restrict__ hs, const float* __restrict__ rw,
            float* __restrict__ disp, float* __restrict__ probs,
            float* __restrict__ loss_out, int ntok)
{
    __shared__ __align__(16) float sw[NE * HDIM];   // weights; reused as hist/ties in finalize
    __shared__ float sW[BLOCK / 32][NE];
    __shared__ float sP[BLOCK / 32][NE];
    __shared__ float red[BLOCK / 32][16];
    __shared__ float sSum[16];
    __shared__ int   s_best, s_tiecnt, s_last;
    __shared__ unsigned s_over;

    // Stage router weights (32KB) into SMEM
    {
        const float4* src = (const float4*)rw;
        float4* dst = (float4*)sw;
        for (int i = threadIdx.x; i < NE * HDIM / 4; i += BLOCK) dst[i] = src[i];
    }
    __syncthreads();

    const int warp = threadIdx.x >> 5;
    const int lane = threadIdx.x & 31;
    const int gwarp = blockIdx.x * (BLOCK / 32) + warp;
    const int nwarps = GRID * (BLOCK / 32);
    const int ngroups = (ntok + 1) >> 1;      // 2 tokens per warp-iteration

    const ulonglong2* __restrict__ hs2 = (const ulonglong2*)hs;  // 256 x 16B per row
    const ulonglong2* __restrict__ w2  = (const ulonglong2*)sw;

    float accW = 0.f;  // lane e<8: running dispatch-weight sum of expert e
    float accP = 0.f;  // lane e<8: running prob sum of expert e

    ulonglong2 hb[3][2];   // prefetch ring: 3 chunk-buffers x 2 tokens
    bool primed = false;
    // prime first group's chunks 0,1 (full-group path only)
    if (gwarp < ngroups) {
        const int t0 = gwarp << 1;
        if (t0 + 2 <= ntok) {
            const ulonglong2* __restrict__ h0 = hs2 + (size_t)t0 * (HDIM / 4);
            hb[0][0] = h0[lane];
            hb[0][1] = h0[(HDIM / 4) + lane];
            hb[1][0] = h0[32 + lane];
            hb[1][1] = h0[(HDIM / 4) + 32 + lane];
            primed = true;
        }
    }

    for (int g = gwarp; g < ngroups; g += nwarps) {
        const int t0 = g << 1;
        const int tcount = (t0 + 2 <= ntok) ? 2 : (ntok - t0);

        unsigned long long acc[2][NE];    // 32 regs
        #pragma unroll
        for (int t = 0; t < 2; t++)
            #pragma unroll
            for (int e = 0; e < NE; e++) acc[t][e] = 0ull;

        const ulonglong2* __restrict__ h0 = hs2 + (size_t)t0 * (HDIM / 4);

        if (tcount == 2 && primed) {
            // depth-2 pipelined mainloop: consume chunk c, prefetch chunk c+2
            #pragma unroll
            for (int c = 0; c < HDIM / 128; c++) {
                const int cur = c % 3;
                if (c + 2 < HDIM / 128) {
                    const int nb = (c + 2) % 3;
                    const int off = (c + 2) * 32 + lane;
                    hb[nb][0] = h0[off];
                    hb[nb][1] = h0[(HDIM / 4) + off];
                }
                const int off = c * 32 + lane;
                #pragma unroll
                for (int e = 0; e < NE; e++) {
                    const ulonglong2 w = w2[e * (HDIM / 4) + off];
                    FMA2(acc[0][e], hb[cur][0].x, w.x);
                    FMA2(acc[0][e], hb[cur][0].y, w.y);
                    FMA2(acc[1][e], hb[cur][1].x, w.x);
                    FMA2(acc[1][e], hb[cur][1].y, w.y);
                }
            }
        } else {
            // rare tail / unprimed path (non-pipelined, same per-token arithmetic)
            for (int c = 0; c < HDIM / 128; c++) {
                const int off = c * 32 + lane;
                for (int t = 0; t < tcount; t++) {
                    const ulonglong2 h = h0[t * (HDIM / 4) + off];
                    #pragma unroll
                    for (int e = 0; e < NE; e++) {
                        const ulonglong2 w = w2[e * (HDIM / 4) + off];
                        FMA2(acc[t][e], h.x, w.x);
                        FMA2(acc[t][e], h.y, w.y);
                    }
                }
            }
        }

        // cross-group prefetch: issue next group's chunks 0,1 BEFORE the epilogue,
        // so global loads are in flight while we do shfl/expf/top-2 work.
        {
            const int gn = g + nwarps;
            primed = false;
            if (gn < ngroups) {
                const int t0n = gn << 1;
                if (t0n + 2 <= ntok) {
                    const ulonglong2* __restrict__ hn = hs2 + (size_t)t0n * (HDIM / 4);
                    hb[0][0] = hn[lane];
                    hb[0][1] = hn[(HDIM / 4) + lane];
                    hb[1][0] = hn[32 + lane];
                    hb[1][1] = hn[(HDIM / 4) + 32 + lane];
                    primed = true;
                }
            }
        }

        // per-token epilogue — arithmetic bit-identical to the round-2/7/8/9 passing kernels
        #pragma unroll
        for (int t = 0; t < 2; t++) {
            if (t >= tcount) break;
            float l[NE];
            #pragma unroll
            for (int e = 0; e < NE; e++) {
                const unsigned long long a = acc[t][e];
                l[e] = __uint_as_float((unsigned)a) + __uint_as_float((unsigned)(a >> 32));
            }
            // Butterfly allreduce across 32 lanes -> ALL lanes hold bit-identical l[0..7]
            #pragma unroll
            for (int s = 16; s > 0; s >>= 1)
                #pragma unroll
                for (int e = 0; e < NE; e++)
                    l[e] += __shfl_xor_sync(0xffffffffu, l[e], s);

            // softmax (TEMPERATURE = 1); lane L computes expf for expert L&7 once,
            // width-8 shfl gather reconstructs ex[0..7] bit-exactly, same sum order.
            float mx = l[0];
            #pragma unroll
            for (int e = 1; e < NE; e++) mx = fmaxf(mx, l[e]);
            const float ex_own = expf(l[lane & 7] - mx);
            float ex[NE], sum = 0.f;
            #pragma unroll
            for (int e = 0; e < NE; e++) {
                ex[e] = __shfl_sync(0xffffffffu, ex_own, e, 8);
                sum += ex[e];
            }
            const float inv = 1.f / sum;
            float p[NE];
            #pragma unroll
            for (int e = 0; e < NE; e++) p[e] = ex[e] * inv;

            // top-2 (lowest index wins ties), renormalize
            int i1 = 0;
            #pragma unroll
            for (int e = 1; e < NE; e++) if (p[e] > p[i1]) i1 = e;
            int i2 = -1;
            #pragma unroll
            for (int e = 0; e < NE; e++)
                if (e != i1 && (i2 < 0 || p[e] > p[i2])) i2 = e;
            const float dsum = p[i1] + p[i2];
            const float d1 = p[i1] / dsum;
            const float d2 = p[i2] / dsum;

            if (lane < NE) {
                const size_t o = (size_t)(t0 + t) * NE + lane;
                probs[o] = p[lane];
                const float dm = (lane == i1) ? d1 : (lane == i2) ? d2 : 0.f;
                disp[o] = dm;
                accP += p[lane];
                accW += dm;
            }
        }
    }

    if (lane < NE) { sW[warp][lane] = accW; sP[warp][lane] = accP; }
    __syncthreads();
    if (threadIdx.x < 16) {
        const int e = threadIdx.x & 7;
        float s = 0.f;
        if (threadIdx.x < 8) {
            #pragma unroll
            for (int w = 0; w < BLOCK / 32; w++) s += sW[w][e];
        } else {
            #pragma unroll
            for (int w = 0; w < BLOCK / 32; w++) s += sP[w][e];
        }
        g_partials[blockIdx.x * 16 + threadIdx.x] = s;
    }
    __syncthreads();

    // ---- last-block election ----
    if (threadIdx.x == 0) {
        __threadfence();
        const int old = atomicAdd(&g_ticket, 1);
        s_last = (old == GRID - 1);
        if (s_last) g_ticket = 0;   // reset for next launch / replay
    }
    __syncthreads();
    if (!s_last) return;

    // =================== finalize (last block only, 256 threads) ===================
    const int tid = threadIdx.x;
    int* hist = (int*)sw;            // weights no longer needed: reuse as hist/ties
    {
        float s = 0.f;
        for (int i = tid; i < GRID * 16; i += BLOCK) s += g_partials[i];   // col = i & 15
        s += __shfl_xor_sync(0xffffffffu, s, 16);   // lanes L and L+16 share a column
        if (lane < 16) red[warp][lane] = s;
    }
    __syncthreads();
    if (tid < 16) {
        float s = 0.f;
        #pragma unroll
        for (int w = 0; w < BLOCK / 32; w++) s += red[w][tid];
        sSum[tid] = s;
    }
    __syncthreads();

    const int cap = (int)(1.25 * (double)ntok / (double)NE);  // 5120 for N=32768

    if (tid == 0) {
        float l = 0.f;
        for (int e = 0; e < NE; e++) l += sSum[e] * sSum[8 + e];
        loss_out[0] = 0.01f * (l / (float)ntok);
        unsigned m = 0;
        for (int e = 0; e < NE; e++)
            if (sSum[e] > (float)cap) m |= 1u << e;
        s_over = m;
    }
    __syncthreads();
    const unsigned over = s_over;
    if (!over) return;  // fast path: statistically always taken for this data

    // Exact radix-select per over-capacity expert (values in (0,1]; positive
    // float bit patterns are order-monotonic). Levels: bits>>20 | (bits>>9)&0x7FF | bits&0x1FF.
    for (int e = 0; e < NE; e++) {
        if (!((over >> e) & 1u)) continue;

        // level 1: bin = bits >> 20  (<= 0x3F8 for v <= 1.0)
        for (int i = tid; i < 2048; i += BLOCK) hist[i] = 0;
        __syncthreads();
        for (int t = tid; t < ntok; t += BLOCK) {
            const float v = disp[(size_t)t * NE + e];
            if (v > 0.f) atomicAdd(&hist[__float_as_uint(v) >> 20], 1);
        }
        __syncthreads();
        suffix_scan256(hist, 2048);
        if (tid == 0) s_best = -1;
        __syncthreads();
        for (int i = tid; i < 2048; i += BLOCK)
            if (hist[i] >= cap) atomicMax(&s_best, i);
        __syncthreads();
        const int b1 = s_best;
        if (b1 < 0) { __syncthreads(); continue; }
        const int A1 = (b1 + 1 < 2048) ? hist[b1 + 1] : 0;
        const int cap2 = cap - A1;
        __syncthreads();

        // level 2: among bits>>20 == b1: bin = (bits >> 9) & 0x7FF
        for (int i = tid; i < 2048; i += BLOCK) hist[i] = 0;
        __syncthreads();
        for (int t = tid; t < ntok; t += BLOCK) {
            const float v = disp[(size_t)t * NE + e];
            if (v > 0.f) {
                const unsigned b = __float_as_uint(v);
                if ((int)(b >> 20) == b1) atomicAdd(&hist[(b >> 9) & 0x7FF], 1);
            }
        }
        __syncthreads();
        suffix_scan256(hist, 2048);
        if (tid == 0) s_best = -1;
        __syncthreads();
        for (int i = tid; i < 2048; i += BLOCK)
            if (hist[i] >= cap2) atomicMax(&s_best, i);
        __syncthreads();
        const int b2 = s_best;
        const int A2 = (b2 + 1 < 2048) ? hist[b2 + 1] : 0;
        const int cap3 = cap2 - A2;
        const unsigned key = ((unsigned)b1 << 11) | (unsigned)b2;   // == bits >> 9
        __syncthreads();

        // level 3: among bits>>9 == key: bin = bits & 0x1FF
        for (int i = tid; i < 512; i += BLOCK) hist[i] = 0;
        __syncthreads();
        for (int t = tid; t < ntok; t += BLOCK) {
            const float v = disp[(size_t)t * NE + e];
            if (v > 0.f) {
                const unsigned b = __float_as_uint(v);
                if ((b >> 9) == key) atomicAdd(&hist[b & 0x1FF], 1);
            }
        }
        __syncthreads();
        suffix_scan256(hist, 512);
        if (tid == 0) s_best = -1;
        __syncthreads();
        for (int i = tid; i < 512; i += BLOCK)
            if (hist[i] >= cap3) atomicMax(&s_best, i);
        __syncthreads();
        const int b3 = s_best;
        const int A3 = (b3 + 1 < 512) ? hist[b3 + 1] : 0;
        const int keep_eq = cap3 - A3;            // ==threshold entries that survive
        const unsigned thr = (key << 9) | (unsigned)b3;
        __syncthreads();

        // apply: zero below threshold; collect exact ties (reuse hist as buffer)
        int* s_ties = hist;
        if (tid == 0) s_tiecnt = 0;
        __syncthreads();
        for (int t = tid; t < ntok; t += BLOCK) {
            const size_t o = (size_t)t * NE + e;
            const float v = disp[o];
            if (v > 0.f) {
                const unsigned b = __float_as_uint(v);
                if (b < thr) {
                    disp[o] = 0.f;
                } else if (b == thr) {
                    const int p = atomicAdd(&s_tiecnt, 1);
                    if (p < 2048) s_ties[p] = t;
                }
            }
        }
        __syncthreads();
        const int tc = (s_tiecnt < 2048) ? s_tiecnt : 2048;
        if (s_tiecnt > keep_eq) {
            // keep the keep_eq ties with smallest token index (jax top_k order)
            for (int i = tid; i < tc; i += BLOCK) {
                const int ti = s_ties[i];
                int rank = 0;
                for (int j = 0; j < tc; j++) rank += (s_ties[j] < ti);
                if (rank >= keep_eq) disp[(size_t)ti * NE + e] = 0.f;
            }
        }
        __syncthreads();
    }
}

extern "C" void kernel_launch(void* const* d_in, const int* in_sizes, int n_in,
                              void* d_out, int out_size)
{
    const float* hs = (const float*)d_in[0];
    const float* rw = (const float*)d_in[1];
    int hsize = in_sizes[0];
    if (n_in >= 2 && in_sizes[0] < in_sizes[1]) {  // defensive: pick the big tensor as hidden
        hs = (const float*)d_in[1];
        rw = (const float*)d_in[0];
        hsize = in_sizes[1];
    }
    const int ntok = hsize / HDIM;

    float* out   = (float*)d_out;
    float* disp  = out;                          // [N, E]
    float* loss  = out + (size_t)ntok * NE;      // scalar
    float* probs = loss + 1;                     // [N, E]

    route_fused<<<GRID, BLOCK>>>(hs, rw, disp, probs, loss, ntok);
}

// round 11
// speedup vs baseline: 1.0848x; 1.0848x over previous
#include <cuda_runtime.h>
#include <cstdint>

#define GRID   444
#define BLOCK  256
#define NE     8
#define HDIM   1024

__device__ float g_partials[GRID * 16];
__device__ int   g_ticket = 0;

// Packed fp32x2 FMA (Blackwell): d.lo += a.lo*b.lo ; d.hi += a.hi*b.hi
#define FMA2(d, a, b) asm("fma.rn.f32x2 %0, %1, %2, %0;" : "+l"(d) : "l"(a), "l"(b))

__device__ __forceinline__ void suffix_scan256(int* h, int n)
{
    // inclusive suffix sums, n <= 2048, 256 threads
    for (int off = 1; off < n; off <<= 1) {
        int v[8]; int c = 0;
        for (int i = threadIdx.x; i < n; i += BLOCK) {
            const int add = (i + off < n) ? h[i + off] : 0;
            v[c++] = h[i] + add;
        }
        __syncthreads();
        c = 0;
        for (int i = threadIdx.x; i < n; i += BLOCK) h[i] = v[c++];
        __syncthreads();
    }
}

__global__ void __launch_bounds__(BLOCK, 3)
route_fused(const float* __restrict__ hs, const float* __restrict__ rw,
            float* __restrict__ disp, float* __restrict__ probs,
            float* __restrict__ loss_out, int ntok)
{
    __shared__ __align__(16) float sw[NE * HDIM];   // weights; reused as hist/ties in finalize
    __shared__ float sW[BLOCK / 32][NE];
    __shared__ float sP[BLOCK / 32][NE];
    __shared__ float red[BLOCK / 32][16];
    __shared__ float sSum[16];
    __shared__ int   s_best, s_tiecnt, s_last;
    __shared__ unsigned s_over;

    // Stage router weights (32KB) into SMEM
    {
        const float4* src = (const float4*)rw;
        float4* dst = (float4*)sw;
        for (int i = threadIdx.x; i < NE * HDIM / 4; i += BLOCK) dst[i] = src[i];
    }
    __syncthreads();

    const int warp = threadIdx.x >> 5;
    const int lane = threadIdx.x & 31;
    const int gwarp = blockIdx.x * (BLOCK / 32) + warp;
    const int nwarps = GRID * (BLOCK / 32);
    const int ngroups = (ntok + 1) >> 1;      // 2 tokens per warp-iteration

    const ulonglong2* __restrict__ hs2 = (const ulonglong2*)hs;  // 256 x 16B per row
    const ulonglong2* __restrict__ w2  = (const ulonglong2*)sw;

    float accW = 0.f;  // lane e<8: running dispatch-weight sum of expert e
    float accP = 0.f;  // lane e<8: running prob sum of expert e

    ulonglong2 hb[3][2];   // prefetch ring: 3 chunk-buffers x 2 tokens
    bool primed = false;
    // prime first group's chunks 0,1 (full-group path only)
    if (gwarp < ngroups) {
        const int t0 = gwarp << 1;
        if (t0 + 2 <= ntok) {
            const ulonglong2* __restrict__ h0 = hs2 + (size_t)t0 * (HDIM / 4);
            hb[0][0] = h0[lane];
            hb[0][1] = h0[(HDIM / 4) + lane];
            hb[1][0] = h0[32 + lane];
            hb[1][1] = h0[(HDIM / 4) + 32 + lane];
            primed = true;
        }
    }

    for (int g = gwarp; g < ngroups; g += nwarps) {
        const int t0 = g << 1;
        const int tcount = (t0 + 2 <= ntok) ? 2 : (ntok - t0);

        // L2 prefetch of this warp's NEXT group (8KB contiguous: 2 token rows).
        // Lane L covers 128B lines 2L and 2L+1. Fire-and-forget; no regs, no smem.
        {
            const int gp = g + nwarps;
            if (gp < ngroups && ((gp << 1) + 2) <= ntok) {
                const char* pf = (const char*)(hs2 + (size_t)(gp << 1) * (HDIM / 4));
                asm volatile("prefetch.global.L2 [%0];" :: "l"(pf + lane * 256));
                asm volatile("prefetch.global.L2 [%0];" :: "l"(pf + lane * 256 + 128));
            }
        }

        unsigned long long acc[2][NE];    // 32 regs
        #pragma unroll
        for (int t = 0; t < 2; t++)
            #pragma unroll
            for (int e = 0; e < NE; e++) acc[t][e] = 0ull;

        const ulonglong2* __restrict__ h0 = hs2 + (size_t)t0 * (HDIM / 4);

        if (tcount == 2 && primed) {
            // depth-2 pipelined mainloop: consume chunk c, prefetch chunk c+2
            #pragma unroll
            for (int c = 0; c < HDIM / 128; c++) {
                const int cur = c % 3;
                if (c + 2 < HDIM / 128) {
                    const int nb = (c + 2) % 3;
                    const int off = (c + 2) * 32 + lane;
                    hb[nb][0] = h0[off];
                    hb[nb][1] = h0[(HDIM / 4) + off];
                }
                const int off = c * 32 + lane;
                #pragma unroll
                for (int e = 0; e < NE; e++) {
                    const ulonglong2 w = w2[e * (HDIM / 4) + off];
                    FMA2(acc[0][e], hb[cur][0].x, w.x);
                    FMA2(acc[0][e], hb[cur][0].y, w.y);
                    FMA2(acc[1][e], hb[cur][1].x, w.x);
                    FMA2(acc[1][e], hb[cur][1].y, w.y);
                }
            }
        } else {
            // rare tail / unprimed path (non-pipelined, same per-token arithmetic)
            for (int c = 0; c < HDIM / 128; c++) {
                const int off = c * 32 + lane;
                for (int t = 0; t < tcount; t++) {
                    const ulonglong2 h = h0[t * (HDIM / 4) + off];
                    #pragma unroll
                    for (int e = 0; e < NE; e++) {
                        const ulonglong2 w = w2[e * (HDIM / 4) + off];
                        FMA2(acc[t][e], h.x, w.x);
                        FMA2(acc[t][e], h.y, w.y);
                    }
                }
            }
        }

        // cross-group register prefetch: issue next group's chunks 0,1 BEFORE the
        // epilogue, so loads are in flight during the shfl/expf/top-2 work.
        {
            const int gn = g + nwarps;
            primed = false;
            if (gn < ngroups) {
                const int t0n = gn << 1;
                if (t0n + 2 <= ntok) {
                    const ulonglong2* __restrict__ hn = hs2 + (size_t)t0n * (HDIM / 4);
                    hb[0][0] = hn[lane];
                    hb[0][1] = hn[(HDIM / 4) + lane];
                    hb[1][0] = hn[32 + lane];
                    hb[1][1] = hn[(HDIM / 4) + 32 + lane];
                    primed = true;
                }
            }
        }

        // per-token epilogue — arithmetic bit-identical to the round-2/7/8/9/10 passing kernels
        #pragma unroll
        for (int t = 0; t < 2; t++) {
            if (t >= tcount) break;
            float l[NE];
            #pragma unroll
            for (int e = 0; e < NE; e++) {
                const unsigned long long a = acc[t][e];
                l[e] = __uint_as_float((unsigned)a) + __uint_as_float((unsigned)(a >> 32));
            }
            // Butterfly allreduce across 32 lanes -> ALL lanes hold bit-identical l[0..7]
            #pragma unroll
            for (int s = 16; s > 0; s >>= 1)
                #pragma unroll
                for (int e = 0; e < NE; e++)
                    l[e] += __shfl_xor_sync(0xffffffffu, l[e], s);

            // softmax (TEMPERATURE = 1); lane L computes expf for expert L&7 once,
            // width-8 shfl gather reconstructs ex[0..7] bit-exactly, same sum order.
            float mx = l[0];
            #pragma unroll
            for (int e = 1; e < NE; e++) mx = fmaxf(mx, l[e]);
            const float ex_own = expf(l[lane & 7] - mx);
            float ex[NE], sum = 0.f;
            #pragma unroll
            for (int e = 0; e < NE; e++) {
                ex[e] = __shfl_sync(0xffffffffu, ex_own, e, 8);
                sum += ex[e];
            }
            const float inv = 1.f / sum;
            float p[NE];
            #pragma unroll
            for (int e = 0; e < NE; e++) p[e] = ex[e] * inv;

            // top-2 (lowest index wins ties), renormalize
            int i1 = 0;
            #pragma unroll
            for (int e = 1; e < NE; e++) if (p[e] > p[i1]) i1 = e;
            int i2 = -1;
            #pragma unroll
            for (int e = 0; e < NE; e++)
                if (e != i1 && (i2 < 0 || p[e] > p[i2])) i2 = e;
            const float dsum = p[i1] + p[i2];
            const float d1 = p[i1] / dsum;
            const float d2 = p[i2] / dsum;

            if (lane < NE) {
                const size_t o = (size_t)(t0 + t) * NE + lane;
                probs[o] = p[lane];
                const float dm = (lane == i1) ? d1 : (lane == i2) ? d2 : 0.f;
                disp[o] = dm;
                accP += p[lane];
                accW += dm;
            }
        }
    }

    if (lane < NE) { sW[warp][lane] = accW; sP[warp][lane] = accP; }
    __syncthreads();
    if (threadIdx.x < 16) {
        const int e = threadIdx.x & 7;
        float s = 0.f;
        if (threadIdx.x < 8) {
            #pragma unroll
            for (int w = 0; w < BLOCK / 32; w++) s += sW[w][e];
        } else {
            #pragma unroll
            for (int w = 0; w < BLOCK / 32; w++) s += sP[w][e];
        }
        g_partials[blockIdx.x * 16 + threadIdx.x] = s;
    }
    __syncthreads();

    // ---- last-block election ----
    if (threadIdx.x == 0) {
        __threadfence();
        const int old = atomicAdd(&g_ticket, 1);
        s_last = (old == GRID - 1);
        if (s_last) g_ticket = 0;   // reset for next launch / replay
    }
    __syncthreads();
    if (!s_last) return;

    // =================== finalize (last block only, 256 threads) ===================
    const int tid = threadIdx.x;
    int* hist = (int*)sw;            // weights no longer needed: reuse as hist/ties
    {
        float s = 0.f;
        for (int i = tid; i < GRID * 16; i += BLOCK) s += g_partials[i];   // col = i & 15
        s += __shfl_xor_sync(0xffffffffu, s, 16);   // lanes L and L+16 share a column
        if (lane < 16) red[warp][lane] = s;
    }
    __syncthreads();
    if (tid < 16) {
        float s = 0.f;
        #pragma unroll
        for (int w = 0; w < BLOCK / 32; w++) s += red[w][tid];
        sSum[tid] = s;
    }
    __syncthreads();

    const int cap = (int)(1.25 * (double)ntok / (double)NE);  // 5120 for N=32768

    if (tid == 0) {
        float l = 0.f;
        for (int e = 0; e < NE; e++) l += sSum[e] * sSum[8 + e];
        loss_out[0] = 0.01f * (l / (float)ntok);
        unsigned m = 0;
        for (int e = 0; e < NE; e++)
            if (sSum[e] > (float)cap) m |= 1u << e;
        s_over = m;
    }
    __syncthreads();
    const unsigned over = s_over;
    if (!over) return;  // fast path: statistically always taken for this data

    // Exact radix-select per over-capacity expert (values in (0,1]; positive
    // float bit patterns are order-monotonic). Levels: bits>>20 | (bits>>9)&0x7FF | bits&0x1FF.
    for (int e = 0; e < NE; e++) {
        if (!((over >> e) & 1u)) continue;

        // level 1: bin = bits >> 20  (<= 0x3F8 for v <= 1.0)
        for (int i = tid; i < 2048; i += BLOCK) hist[i] = 0;
        __syncthreads();
        for (int t = tid; t < ntok; t += BLOCK) {
            const float v = disp[(size_t)t * NE + e];
            if (v > 0.f) atomicAdd(&hist[__float_as_uint(v) >> 20], 1);
        }
        __syncthreads();
        suffix_scan256(hist, 2048);
        if (tid == 0) s_best = -1;
        __syncthreads();
        for (int i = tid; i < 2048; i += BLOCK)
            if (hist[i] >= cap) atomicMax(&s_best, i);
        __syncthreads();
        const int b1 = s_best;
        if (b1 < 0) { __syncthreads(); continue; }
        const int A1 = (b1 + 1 < 2048) ? hist[b1 + 1] : 0;
        const int cap2 = cap - A1;
        __syncthreads();

        // level 2: among bits>>20 == b1: bin = (bits >> 9) & 0x7FF
        for (int i = tid; i < 2048; i += BLOCK) hist[i] = 0;
        __syncthreads();
        for (int t = tid; t < ntok; t += BLOCK) {
            const float v = disp[(size_t)t * NE + e];
            if (v > 0.f) {
                const unsigned b = __float_as_uint(v);
                if ((int)(b >> 20) == b1) atomicAdd(&hist[(b >> 9) & 0x7FF], 1);
            }
        }
        __syncthreads();
        suffix_scan256(hist, 2048);
        if (tid == 0) s_best = -1;
        __syncthreads();
        for (int i = tid; i < 2048; i += BLOCK)
            if (hist[i] >= cap2) atomicMax(&s_best, i);
        __syncthreads();
        const int b2 = s_best;
        const int A2 = (b2 + 1 < 2048) ? hist[b2 + 1] : 0;
        const int cap3 = cap2 - A2;
        const unsigned key = ((unsigned)b1 << 11) | (unsigned)b2;   // == bits >> 9
        __syncthreads();

        // level 3: among bits>>9 == key: bin = bits & 0x1FF
        for (int i = tid; i < 512; i += BLOCK) hist[i] = 0;
        __syncthreads();
        for (int t = tid; t < ntok; t += BLOCK) {
            const float v = disp[(size_t)t * NE + e];
            if (v > 0.f) {
                const unsigned b = __float_as_uint(v);
                if ((b >> 9) == key) atomicAdd(&hist[b & 0x1FF], 1);
            }
        }
        __syncthreads();
        suffix_scan256(hist, 512);
        if (tid == 0) s_best = -1;
        __syncthreads();
        for (int i = tid; i < 512; i += BLOCK)
            if (hist[i] >= cap3) atomicMax(&s_best, i);
        __syncthreads();
        const int b3 = s_best;
        const int A3 = (b3 + 1 < 512) ? hist[b3 + 1] : 0;
        const int keep_eq = cap3 - A3;            // ==threshold entries that survive
        const unsigned thr = (key << 9) | (unsigned)b3;
        __syncthreads();

        // apply: zero below threshold; collect exact ties (reuse hist as buffer)
        int* s_ties = hist;
        if (tid == 0) s_tiecnt = 0;
        __syncthreads();
        for (int t = tid; t < ntok; t += BLOCK) {
            const size_t o = (size_t)t * NE + e;
            const float v = disp[o];
            if (v > 0.f) {
                const unsigned b = __float_as_uint(v);
                if (b < thr) {
                    disp[o] = 0.f;
                } else if (b == thr) {
                    const int p = atomicAdd(&s_tiecnt, 1);
                    if (p < 2048) s_ties[p] = t;
                }
            }
        }
        __syncthreads();
        const int tc = (s_tiecnt < 2048) ? s_tiecnt : 2048;
        if (s_tiecnt > keep_eq) {
            // keep the keep_eq ties with smallest token index (jax top_k order)
            for (int i = tid; i < tc; i += BLOCK) {
                const int ti = s_ties[i];
                int rank = 0;
                for (int j = 0; j < tc; j++) rank += (s_ties[j] < ti);
                if (rank >= keep_eq) disp[(size_t)ti * NE + e] = 0.f;
            }
        }
        __syncthreads();
    }
}

extern "C" void kernel_launch(void* const* d_in, const int* in_sizes, int n_in,
                              void* d_out, int out_size)
{
    const float* hs = (const float*)d_in[0];
    const float* rw = (const float*)d_in[1];
    int hsize = in_sizes[0];
    if (n_in >= 2 && in_sizes[0] < in_sizes[1]) {  // defensive: pick the big tensor as hidden
        hs = (const float*)d_in[1];
        rw = (const float*)d_in[0];
        hsize = in_sizes[1];
    }
    const int ntok = hsize / HDIM;

    float* out   = (float*)d_out;
    float* disp  = out;                          // [N, E]
    float* loss  = out + (size_t)ntok * NE;      // scalar
    float* probs = loss + 1;                     // [N, E]

    route_fused<<<GRID, BLOCK>>>(hs, rw, disp, probs, loss, ntok);
}

// round 12
// speedup vs baseline: 1.1192x; 1.0317x over previous
#include <cuda_runtime.h>
#include <cstdint>

#define GRID   296
#define BLOCK  256
#define NE     8
#define HDIM   1024

__device__ float g_partials[GRID * 16];
__device__ int   g_ticket = 0;

// Packed fp32x2 FMA (Blackwell): d.lo += a.lo*b.lo ; d.hi += a.hi*b.hi
#define FMA2(d, a, b) asm("fma.rn.f32x2 %0, %1, %2, %0;" : "+l"(d) : "l"(a), "l"(b))

__device__ __forceinline__ void suffix_scan256(int* h, int n)
{
    // inclusive suffix sums, n <= 2048, 256 threads
    for (int off = 1; off < n; off <<= 1) {
        int v[8]; int c = 0;
        for (int i = threadIdx.x; i < n; i += BLOCK) {
            const int add = (i + off < n) ? h[i + off] : 0;
            v[c++] = h[i] + add;
        }
        __syncthreads();
        c = 0;
        for (int i = threadIdx.x; i < n; i += BLOCK) h[i] = v[c++];
        __syncthreads();
    }
}

__global__ void __launch_bounds__(BLOCK, 2)
route_fused(const float* __restrict__ hs, const float* __restrict__ rw,
            float* __restrict__ disp, float* __restrict__ probs,
            float* __restrict__ loss_out, int ntok)
{
    __shared__ __align__(16) float sw[NE * HDIM];   // weights; reused as hist/ties in finalize
    __shared__ float sW[BLOCK / 32][NE];
    __shared__ float sP[BLOCK / 32][NE];
    __shared__ float red[BLOCK / 32][16];
    __shared__ float sSum[16];
    __shared__ int   s_best, s_tiecnt, s_last;
    __shared__ unsigned s_over;

    // Stage router weights (32KB) into SMEM
    {
        const float4* src = (const float4*)rw;
        float4* dst = (float4*)sw;
        for (int i = threadIdx.x; i < NE * HDIM / 4; i += BLOCK) dst[i] = src[i];
    }
    __syncthreads();

    const int warp = threadIdx.x >> 5;
    const int lane = threadIdx.x & 31;
    const int gwarp = blockIdx.x * (BLOCK / 32) + warp;
    const int nwarps = GRID * (BLOCK / 32);
    const int ngroups = (ntok + 3) >> 2;      // 4 tokens per warp-iteration

    const ulonglong2* __restrict__ hs2 = (const ulonglong2*)hs;  // 256 x 16B per row
    const ulonglong2* __restrict__ w2  = (const ulonglong2*)sw;

    float accW = 0.f;  // running dispatch-weight sum, this lane's (tok,e) slot
    float accP = 0.f;  // running prob sum

    for (int g = gwarp; g < ngroups; g += nwarps) {
        const int t0 = g << 2;
        const int tcount = (t0 + 4 <= ntok) ? 4 : (ntok - t0);

        // L2 prefetch of this warp's NEXT group (16KB contiguous: 4 token rows)
        {
            const int gp = g + nwarps;
            if (gp < ngroups && ((gp << 2) + 4) <= ntok) {
                const char* pf = (const char*)(hs2 + (size_t)(gp << 2) * (HDIM / 4));
                asm volatile("prefetch.global.L2 [%0];" :: "l"(pf + lane * 512));
                asm volatile("prefetch.global.L2 [%0];" :: "l"(pf + lane * 512 + 128));
                asm volatile("prefetch.global.L2 [%0];" :: "l"(pf + lane * 512 + 256));
                asm volatile("prefetch.global.L2 [%0];" :: "l"(pf + lane * 512 + 384));
            }
        }

        unsigned long long acc[4][NE];    // 64 regs
        #pragma unroll
        for (int t = 0; t < 4; t++)
            #pragma unroll
            for (int e = 0; e < NE; e++) acc[t][e] = 0ull;

        const ulonglong2* __restrict__ h0 = hs2 + (size_t)t0 * (HDIM / 4);

        if (tcount == 4) {
            // mainloop: EXACT round-2 proven arithmetic (T=4, FMA2, chunk-serial)
            #pragma unroll
            for (int c = 0; c < HDIM / 128; c++) {
                const int off = c * 32 + lane;
                ulonglong2 h[4];
                #pragma unroll
                for (int t = 0; t < 4; t++) h[t] = h0[t * (HDIM / 4) + off];
                #pragma unroll
                for (int e = 0; e < NE; e++) {
                    const ulonglong2 w = w2[e * (HDIM / 4) + off];
                    #pragma unroll
                    for (int t = 0; t < 4; t++) {
                        FMA2(acc[t][e], h[t].x, w.x);
                        FMA2(acc[t][e], h[t].y, w.y);
                    }
                }
            }

            // lo+hi combine (same op as all passing rounds): a[k] = logit partial
            // of value k = t*8+e for (t = k>>3, e = k&7)
            float a[32];
            #pragma unroll
            for (int t = 0; t < 4; t++)
                #pragma unroll
                for (int e = 0; e < NE; e++) {
                    const unsigned long long v = acc[t][e];
                    a[t * NE + e] = __uint_as_float((unsigned)v) +
                                    __uint_as_float((unsigned)(v >> 32));
                }

            // transpose-reduce: stages s=16..1 combine lane pairs (L, L^s) with
            // own+other adds -> bit-identical to the per-value butterfly.
            // After all stages, lane L holds the full logit of value k = L.
            #pragma unroll
            for (int s = 16; s > 0; s >>= 1) {
                const bool hi = (lane & s) != 0;
                #pragma unroll
                for (int j = 0; j < 32; j++) {
                    if (j >= s) break;
                    const float give = hi ? a[j] : a[j + s];
                    const float got  = __shfl_xor_sync(0xffffffffu, give, s);
                    const float keep = hi ? a[j + s] : a[j];
                    a[j] = keep + got;
                }
            }
            const float l_own = a[0];
            const int   e_own = lane & 7;
            const int   base  = lane & ~7;   // first lane of this token's 8-lane slice

            // gather this token's 8 logits; serial max (same order as before)
            float ls[NE];
            #pragma unroll
            for (int e = 0; e < NE; e++)
                ls[e] = __shfl_sync(0xffffffffu, l_own, base | e);
            float mx = ls[0];
            #pragma unroll
            for (int e = 1; e < NE; e++) mx = fmaxf(mx, ls[e]);

            // one expf per lane; gather; serial sum ascending (identical order)
            const float ex_own = expf(l_own - mx);
            float ex[NE], sum = 0.f;
            #pragma unroll
            for (int e = 0; e < NE; e++) {
                ex[e] = __shfl_sync(0xffffffffu, ex_own, base | e);
                sum += ex[e];
            }
            const float inv = 1.f / sum;
            float p[NE];
            #pragma unroll
            for (int e = 0; e < NE; e++) p[e] = ex[e] * inv;

            // top-2 (identical serial loops -> identical decisions)
            int i1 = 0;
            #pragma unroll
            for (int e = 1; e < NE; e++) if (p[e] > p[i1]) i1 = e;
            int i2 = -1;
            #pragma unroll
            for (int e = 0; e < NE; e++)
                if (e != i1 && (i2 < 0 || p[e] > p[i2])) i2 = e;
            const float dsum = p[i1] + p[i2];
            const float d1 = p[i1] / dsum;
            const float d2 = p[i2] / dsum;

            // fully-coalesced 128B writes: lane L covers (token t0+(L>>3), expert L&7)
            const float p_own = p[e_own];
            const float dm = (e_own == i1) ? d1 : (e_own == i2) ? d2 : 0.f;
            const size_t o = (size_t)t0 * NE + lane;
            probs[o] = p_own;
            disp[o]  = dm;
            accP += p_own;
            accW += dm;
        } else {
            // tail (<4 tokens): non-pipelined, per-token butterfly epilogue
            for (int c = 0; c < HDIM / 128; c++) {
                const int off = c * 32 + lane;
                for (int t = 0; t < tcount; t++) {
                    const ulonglong2 h = h0[t * (HDIM / 4) + off];
                    #pragma unroll
                    for (int e = 0; e < NE; e++) {
                        const ulonglong2 w = w2[e * (HDIM / 4) + off];
                        FMA2(acc[t][e], h.x, w.x);
                        FMA2(acc[t][e], h.y, w.y);
                    }
                }
            }
            for (int t = 0; t < tcount; t++) {
                float l[NE];
                #pragma unroll
                for (int e = 0; e < NE; e++) {
                    const unsigned long long v = acc[t][e];
                    l[e] = __uint_as_float((unsigned)v) + __uint_as_float((unsigned)(v >> 32));
                }
                #pragma unroll
                for (int s = 16; s > 0; s >>= 1)
                    #pragma unroll
                    for (int e = 0; e < NE; e++)
                        l[e] += __shfl_xor_sync(0xffffffffu, l[e], s);
                float mx = l[0];
                #pragma unroll
                for (int e = 1; e < NE; e++) mx = fmaxf(mx, l[e]);
                float ex[NE], sum = 0.f;
                #pragma unroll
                for (int e = 0; e < NE; e++) { ex[e] = expf(l[e] - mx); sum += ex[e]; }
                const float inv = 1.f / sum;
                float p[NE];
                #pragma unroll
                for (int e = 0; e < NE; e++) p[e] = ex[e] * inv;
                int i1 = 0;
                #pragma unroll
                for (int e = 1; e < NE; e++) if (p[e] > p[i1]) i1 = e;
                int i2 = -1;
                #pragma unroll
                for (int e = 0; e < NE; e++)
                    if (e != i1 && (i2 < 0 || p[e] > p[i2])) i2 = e;
                const float dsum = p[i1] + p[i2];
                const float d1 = p[i1] / dsum;
                const float d2 = p[i2] / dsum;
                if (lane < NE) {
                    const size_t o = (size_t)(t0 + t) * NE + lane;
                    probs[o] = p[lane];
                    const float dm = (lane == i1) ? d1 : (lane == i2) ? d2 : 0.f;
                    disp[o] = dm;
                    accP += p[lane];
                    accW += dm;
                }
            }
        }
    }

    // combine lanes sharing the same expert (xor over token bits 3,4)
    accW += __shfl_xor_sync(0xffffffffu, accW, 8);
    accW += __shfl_xor_sync(0xffffffffu, accW, 16);
    accP += __shfl_xor_sync(0xffffffffu, accP, 8);
    accP += __shfl_xor_sync(0xffffffffu, accP, 16);

    if (lane < NE) { sW[warp][lane] = accW; sP[warp][lane] = accP; }
    __syncthreads();
    if (threadIdx.x < 16) {
        const int e = threadIdx.x & 7;
        float s = 0.f;
        if (threadIdx.x < 8) {
            #pragma unroll
            for (int w = 0; w < BLOCK / 32; w++) s += sW[w][e];
        } else {
            #pragma unroll
            for (int w = 0; w < BLOCK / 32; w++) s += sP[w][e];
        }
        g_partials[blockIdx.x * 16 + threadIdx.x] = s;
    }
    __syncthreads();

    // ---- last-block election ----
    if (threadIdx.x == 0) {
        __threadfence();
        const int old = atomicAdd(&g_ticket, 1);
        s_last = (old == GRID - 1);
        if (s_last) g_ticket = 0;   // reset for next launch / replay
    }
    __syncthreads();
    if (!s_last) return;

    // =================== finalize (last block only, 256 threads) ===================
    const int tid = threadIdx.x;
    int* hist = (int*)sw;            // weights no longer needed: reuse as hist/ties
    {
        float s = 0.f;
        for (int i = tid; i < GRID * 16; i += BLOCK) s += g_partials[i];   // col = i & 15
        s += __shfl_xor_sync(0xffffffffu, s, 16);   // lanes L and L+16 share a column
        if (lane < 16) red[warp][lane] = s;
    }
    __syncthreads();
    if (tid < 16) {
        float s = 0.f;
        #pragma unroll
        for (int w = 0; w < BLOCK / 32; w++) s += red[w][tid];
        sSum[tid] = s;
    }
    __syncthreads();

    const int cap = (int)(1.25 * (double)ntok / (double)NE);  // 5120 for N=32768

    if (tid == 0) {
        float l = 0.f;
        for (int e = 0; e < NE; e++) l += sSum[e] * sSum[8 + e];
        loss_out[0] = 0.01f * (l / (float)ntok);
        unsigned m = 0;
        for (int e = 0; e < NE; e++)
            if (sSum[e] > (float)cap) m |= 1u << e;
        s_over = m;
    }
    __syncthreads();
    const unsigned over = s_over;
    if (!over) return;  // fast path: statistically always taken for this data

    // Exact radix-select per over-capacity expert (values in (0,1]; positive
    // float bit patterns are order-monotonic). Levels: bits>>20 | (bits>>9)&0x7FF | bits&0x1FF.
    for (int e = 0; e < NE; e++) {
        if (!((over >> e) & 1u)) continue;

        // level 1: bin = bits >> 20  (<= 0x3F8 for v <= 1.0)
        for (int i = tid; i < 2048; i += BLOCK) hist[i] = 0;
        __syncthreads();
        for (int t = tid; t < ntok; t += BLOCK) {
            const float v = disp[(size_t)t * NE + e];
            if (v > 0.f) atomicAdd(&hist[__float_as_uint(v) >> 20], 1);
        }
        __syncthreads();
        suffix_scan256(hist, 2048);
        if (tid == 0) s_best = -1;
        __syncthreads();
        for (int i = tid; i < 2048; i += BLOCK)
            if (hist[i] >= cap) atomicMax(&s_best, i);
        __syncthreads();
        const int b1 = s_best;
        if (b1 < 0) { __syncthreads(); continue; }
        const int A1 = (b1 + 1 < 2048) ? hist[b1 + 1] : 0;
        const int cap2 = cap - A1;
        __syncthreads();

        // level 2: among bits>>20 == b1: bin = (bits >> 9) & 0x7FF
        for (int i = tid; i < 2048; i += BLOCK) hist[i] = 0;
        __syncthreads();
        for (int t = tid; t < ntok; t += BLOCK) {
            const float v = disp[(size_t)t * NE + e];
            if (v > 0.f) {
                const unsigned b = __float_as_uint(v);
                if ((int)(b >> 20) == b1) atomicAdd(&hist[(b >> 9) & 0x7FF], 1);
            }
        }
        __syncthreads();
        suffix_scan256(hist, 2048);
        if (tid == 0) s_best = -1;
        __syncthreads();
        for (int i = tid; i < 2048; i += BLOCK)
            if (hist[i] >= cap2) atomicMax(&s_best, i);
        __syncthreads();
        const int b2 = s_best;
        const int A2 = (b2 + 1 < 2048) ? hist[b2 + 1] : 0;
        const int cap3 = cap2 - A2;
        const unsigned key = ((unsigned)b1 << 11) | (unsigned)b2;   // == bits >> 9
        __syncthreads();

        // level 3: among bits>>9 == key: bin = bits & 0x1FF
        for (int i = tid; i < 512; i += BLOCK) hist[i] = 0;
        __syncthreads();
        for (int t = tid; t < ntok; t += BLOCK) {
            const float v = disp[(size_t)t * NE + e];
            if (v > 0.f) {
                const unsigned b = __float_as_uint(v);
                if ((b >> 9) == key) atomicAdd(&hist[b & 0x1FF], 1);
            }
        }
        __syncthreads();
        suffix_scan256(hist, 512);
        if (tid == 0) s_best = -1;
        __syncthreads();
        for (int i = tid; i < 512; i += BLOCK)
            if (hist[i] >= cap3) atomicMax(&s_best, i);
        __syncthreads();
        const int b3 = s_best;
        const int A3 = (b3 + 1 < 512) ? hist[b3 + 1] : 0;
        const int keep_eq = cap3 - A3;            // ==threshold entries that survive
        const unsigned thr = (key << 9) | (unsigned)b3;
        __syncthreads();

        // apply: zero below threshold; collect exact ties (reuse hist as buffer)
        int* s_ties = hist;
        if (tid == 0) s_tiecnt = 0;
        __syncthreads();
        for (int t = tid; t < ntok; t += BLOCK) {
            const size_t o = (size_t)t * NE + e;
            const float v = disp[o];
            if (v > 0.f) {
                const unsigned b = __float_as_uint(v);
                if (b < thr) {
                    disp[o] = 0.f;
                } else if (b == thr) {
                    const int p = atomicAdd(&s_tiecnt, 1);
                    if (p < 2048) s_ties[p] = t;
                }
            }
        }
        __syncthreads();
        const int tc = (s_tiecnt < 2048) ? s_tiecnt : 2048;
        if (s_tiecnt > keep_eq) {
            // keep the keep_eq ties with smallest token index (jax top_k order)
            for (int i = tid; i < tc; i += BLOCK) {
                const int ti = s_ties[i];
                int rank = 0;
                for (int j = 0; j < tc; j++) rank += (s_ties[j] < ti);
                if (rank >= keep_eq) disp[(size_t)ti * NE + e] = 0.f;
            }
        }
        __syncthreads();
    }
}

extern "C" void kernel_launch(void* const* d_in, const int* in_sizes, int n_in,
                              void* d_out, int out_size)
{
    const float* hs = (const float*)d_in[0];
    const float* rw = (const float*)d_in[1];
    int hsize = in_sizes[0];
    if (n_in >= 2 && in_sizes[0] < in_sizes[1]) {  // defensive: pick the big tensor as hidden
        hs = (const float*)d_in[1];
        rw = (const float*)d_in[0];
        hsize = in_sizes[1];
    }
    const int ntok = hsize / HDIM;

    float* out   = (float*)d_out;
    float* disp  = out;                          // [N, E]
    float* loss  = out + (size_t)ntok * NE;      // scalar
    float* probs = loss + 1;                     // [N, E]

    route_fused<<<GRID, BLOCK>>>(hs, rw, disp, probs, loss, ntok);
}

// round 13
// speedup vs baseline: 1.1228x; 1.0032x over previous
#include <cuda_runtime.h>
#include <cstdint>

#define GRID   296
#define BLOCK  256
#define NE     8
#define HDIM   1024

__device__ float g_partials[GRID * 16];
__device__ int   g_ticket = 0;

// Packed fp32x2 FMA (Blackwell): d.lo += a.lo*b.lo ; d.hi += a.hi*b.hi
#define FMA2(d, a, b) asm("fma.rn.f32x2 %0, %1, %2, %0;" : "+l"(d) : "l"(a), "l"(b))

__device__ __forceinline__ void suffix_scan256(int* h, int n)
{
    // inclusive suffix sums, n <= 2048, 256 threads
    for (int off = 1; off < n; off <<= 1) {
        int v[8]; int c = 0;
        for (int i = threadIdx.x; i < n; i += BLOCK) {
            const int add = (i + off < n) ? h[i + off] : 0;
            v[c++] = h[i] + add;
        }
        __syncthreads();
        c = 0;
        for (int i = threadIdx.x; i < n; i += BLOCK) h[i] = v[c++];
        __syncthreads();
    }
}

__global__ void __launch_bounds__(BLOCK, 2)
route_fused(const float* __restrict__ hs, const float* __restrict__ rw,
            float* __restrict__ disp, float* __restrict__ probs,
            float* __restrict__ loss_out, int ntok)
{
    __shared__ __align__(16) float sw[NE * HDIM];   // weights; reused as hist/ties in finalize
    __shared__ float sW[BLOCK / 32][NE];
    __shared__ float sP[BLOCK / 32][NE];
    __shared__ float red[BLOCK / 32][16];
    __shared__ float sSum[16];
    __shared__ int   s_best, s_tiecnt, s_last;
    __shared__ unsigned s_over;

    // Stage router weights (32KB) into SMEM
    {
        const float4* src = (const float4*)rw;
        float4* dst = (float4*)sw;
        for (int i = threadIdx.x; i < NE * HDIM / 4; i += BLOCK) dst[i] = src[i];
    }
    __syncthreads();

    const int warp = threadIdx.x >> 5;
    const int lane = threadIdx.x & 31;
    const int gwarp = blockIdx.x * (BLOCK / 32) + warp;
    const int nwarps = GRID * (BLOCK / 32);
    const int ngroups = (ntok + 3) >> 2;      // 4 tokens per warp-iteration

    const ulonglong2* __restrict__ hs2 = (const ulonglong2*)hs;  // 256 x 16B per row
    const ulonglong2* __restrict__ w2  = (const ulonglong2*)sw;

    float accW = 0.f;  // running dispatch-weight sum, this lane's (tok,e) slot
    float accP = 0.f;  // running prob sum

    for (int g = gwarp; g < ngroups; g += nwarps) {
        const int t0 = g << 2;
        const int tcount = (t0 + 4 <= ntok) ? 4 : (ntok - t0);

        // L2 prefetch of this warp's NEXT group (16KB contiguous: 4 token rows)
        {
            const int gp = g + nwarps;
            if (gp < ngroups && ((gp << 2) + 4) <= ntok) {
                const char* pf = (const char*)(hs2 + (size_t)(gp << 2) * (HDIM / 4));
                asm volatile("prefetch.global.L2 [%0];" :: "l"(pf + lane * 512));
                asm volatile("prefetch.global.L2 [%0];" :: "l"(pf + lane * 512 + 128));
                asm volatile("prefetch.global.L2 [%0];" :: "l"(pf + lane * 512 + 256));
                asm volatile("prefetch.global.L2 [%0];" :: "l"(pf + lane * 512 + 384));
            }
        }

        unsigned long long acc[4][NE];    // 64 regs
        #pragma unroll
        for (int t = 0; t < 4; t++)
            #pragma unroll
            for (int e = 0; e < NE; e++) acc[t][e] = 0ull;

        const ulonglong2* __restrict__ h0 = hs2 + (size_t)t0 * (HDIM / 4);

        if (tcount == 4) {
            // double-buffered mainloop: chunk c+1's 4 LDG.128 issue before chunk c's
            // FMAs. Chunk consumption order + FMA2 sequence identical to R2/R12.
            ulonglong2 hb[2][4];          // 32 regs
            #pragma unroll
            for (int t = 0; t < 4; t++) hb[0][t] = h0[t * (HDIM / 4) + lane];

            #pragma unroll
            for (int c = 0; c < HDIM / 128; c++) {
                const int cur = c & 1, nxt = cur ^ 1;
                if (c + 1 < HDIM / 128) {
                    const int offn = (c + 1) * 32 + lane;
                    #pragma unroll
                    for (int t = 0; t < 4; t++) hb[nxt][t] = h0[t * (HDIM / 4) + offn];
                }
                const int off = c * 32 + lane;
                #pragma unroll
                for (int e = 0; e < NE; e++) {
                    const ulonglong2 w = w2[e * (HDIM / 4) + off];
                    #pragma unroll
                    for (int t = 0; t < 4; t++) {
                        FMA2(acc[t][e], hb[cur][t].x, w.x);
                        FMA2(acc[t][e], hb[cur][t].y, w.y);
                    }
                }
            }

            // lo+hi combine: a[k] = partial logit of value k = t*8+e
            float a[32];
            #pragma unroll
            for (int t = 0; t < 4; t++)
                #pragma unroll
                for (int e = 0; e < NE; e++) {
                    const unsigned long long v = acc[t][e];
                    a[t * NE + e] = __uint_as_float((unsigned)v) +
                                    __uint_as_float((unsigned)(v >> 32));
                }

            // transpose-reduce (bit-identical to per-value butterfly; proven R12)
            #pragma unroll
            for (int s = 16; s > 0; s >>= 1) {
                const bool hi = (lane & s) != 0;
                #pragma unroll
                for (int j = 0; j < 32; j++) {
                    if (j >= s) break;
                    const float give = hi ? a[j] : a[j + s];
                    const float got  = __shfl_xor_sync(0xffffffffu, give, s);
                    const float keep = hi ? a[j + s] : a[j];
                    a[j] = keep + got;
                }
            }
            const float l_own = a[0];
            const int   e_own = lane & 7;
            const int   base  = lane & ~7;

            float ls[NE];
            #pragma unroll
            for (int e = 0; e < NE; e++)
                ls[e] = __shfl_sync(0xffffffffu, l_own, base | e);
            float mx = ls[0];
            #pragma unroll
            for (int e = 1; e < NE; e++) mx = fmaxf(mx, ls[e]);

            const float ex_own = expf(l_own - mx);
            float ex[NE], sum = 0.f;
            #pragma unroll
            for (int e = 0; e < NE; e++) {
                ex[e] = __shfl_sync(0xffffffffu, ex_own, base | e);
                sum += ex[e];
            }
            const float inv = 1.f / sum;
            float p[NE];
            #pragma unroll
            for (int e = 0; e < NE; e++) p[e] = ex[e] * inv;

            int i1 = 0;
            #pragma unroll
            for (int e = 1; e < NE; e++) if (p[e] > p[i1]) i1 = e;
            int i2 = -1;
            #pragma unroll
            for (int e = 0; e < NE; e++)
                if (e != i1 && (i2 < 0 || p[e] > p[i2])) i2 = e;
            const float dsum = p[i1] + p[i2];
            const float d1 = p[i1] / dsum;
            const float d2 = p[i2] / dsum;

            const float p_own = p[e_own];
            const float dm = (e_own == i1) ? d1 : (e_own == i2) ? d2 : 0.f;
            const size_t o = (size_t)t0 * NE + lane;
            probs[o] = p_own;
            disp[o]  = dm;
            accP += p_own;
            accW += dm;
        } else {
            // tail (<4 tokens): non-pipelined, per-token butterfly epilogue
            for (int c = 0; c < HDIM / 128; c++) {
                const int off = c * 32 + lane;
                for (int t = 0; t < tcount; t++) {
                    const ulonglong2 h = h0[t * (HDIM / 4) + off];
                    #pragma unroll
                    for (int e = 0; e < NE; e++) {
                        const ulonglong2 w = w2[e * (HDIM / 4) + off];
                        FMA2(acc[t][e], h.x, w.x);
                        FMA2(acc[t][e], h.y, w.y);
                    }
                }
            }
            for (int t = 0; t < tcount; t++) {
                float l[NE];
                #pragma unroll
                for (int e = 0; e < NE; e++) {
                    const unsigned long long v = acc[t][e];
                    l[e] = __uint_as_float((unsigned)v) + __uint_as_float((unsigned)(v >> 32));
                }
                #pragma unroll
                for (int s = 16; s > 0; s >>= 1)
                    #pragma unroll
                    for (int e = 0; e < NE; e++)
                        l[e] += __shfl_xor_sync(0xffffffffu, l[e], s);
                float mx = l[0];
                #pragma unroll
                for (int e = 1; e < NE; e++) mx = fmaxf(mx, l[e]);
                float ex[NE], sum = 0.f;
                #pragma unroll
                for (int e = 0; e < NE; e++) { ex[e] = expf(l[e] - mx); sum += ex[e]; }
                const float inv = 1.f / sum;
                float p[NE];
                #pragma unroll
                for (int e = 0; e < NE; e++) p[e] = ex[e] * inv;
                int i1 = 0;
                #pragma unroll
                for (int e = 1; e < NE; e++) if (p[e] > p[i1]) i1 = e;
                int i2 = -1;
                #pragma unroll
                for (int e = 0; e < NE; e++)
                    if (e != i1 && (i2 < 0 || p[e] > p[i2])) i2 = e;
                const float dsum = p[i1] + p[i2];
                const float d1 = p[i1] / dsum;
                const float d2 = p[i2] / dsum;
                if (lane < NE) {
                    const size_t o = (size_t)(t0 + t) * NE + lane;
                    probs[o] = p[lane];
                    const float dm = (lane == i1) ? d1 : (lane == i2) ? d2 : 0.f;
                    disp[o] = dm;
                    accP += p[lane];
                    accW += dm;
                }
            }
        }
    }

    // combine lanes sharing the same expert (xor over token bits 3,4)
    accW += __shfl_xor_sync(0xffffffffu, accW, 8);
    accW += __shfl_xor_sync(0xffffffffu, accW, 16);
    accP += __shfl_xor_sync(0xffffffffu, accP, 8);
    accP += __shfl_xor_sync(0xffffffffu, accP, 16);

    if (lane < NE) { sW[warp][lane] = accW; sP[warp][lane] = accP; }
    __syncthreads();
    if (threadIdx.x < 16) {
        const int e = threadIdx.x & 7;
        float s = 0.f;
        if (threadIdx.x < 8) {
            #pragma unroll
            for (int w = 0; w < BLOCK / 32; w++) s += sW[w][e];
        } else {
            #pragma unroll
            for (int w = 0; w < BLOCK / 32; w++) s += sP[w][e];
        }
        g_partials[blockIdx.x * 16 + threadIdx.x] = s;
    }
    __syncthreads();

    // ---- last-block election ----
    if (threadIdx.x == 0) {
        __threadfence();
        const int old = atomicAdd(&g_ticket, 1);
        s_last = (old == GRID - 1);
        if (s_last) g_ticket = 0;   // reset for next launch / replay
    }
    __syncthreads();
    if (!s_last) return;

    // =================== finalize (last block only, 256 threads) ===================
    const int tid = threadIdx.x;
    int* hist = (int*)sw;            // weights no longer needed: reuse as hist/ties
    {
        float s = 0.f;
        for (int i = tid; i < GRID * 16; i += BLOCK) s += g_partials[i];   // col = i & 15
        s += __shfl_xor_sync(0xffffffffu, s, 16);   // lanes L and L+16 share a column
        if (lane < 16) red[warp][lane] = s;
    }
    __syncthreads();
    if (tid < 16) {
        float s = 0.f;
        #pragma unroll
        for (int w = 0; w < BLOCK / 32; w++) s += red[w][tid];
        sSum[tid] = s;
    }
    __syncthreads();

    const int cap = (int)(1.25 * (double)ntok / (double)NE);  // 5120 for N=32768

    if (tid == 0) {
        float l = 0.f;
        for (int e = 0; e < NE; e++) l += sSum[e] * sSum[8 + e];
        loss_out[0] = 0.01f * (l / (float)ntok);
        unsigned m = 0;
        for (int e = 0; e < NE; e++)
            if (sSum[e] > (float)cap) m |= 1u << e;
        s_over = m;
    }
    __syncthreads();
    const unsigned over = s_over;
    if (!over) return;  // fast path: statistically always taken for this data

    // Exact radix-select per over-capacity expert (values in (0,1]; positive
    // float bit patterns are order-monotonic). Levels: bits>>20 | (bits>>9)&0x7FF | bits&0x1FF.
    for (int e = 0; e < NE; e++) {
        if (!((over >> e) & 1u)) continue;

        // level 1: bin = bits >> 20  (<= 0x3F8 for v <= 1.0)
        for (int i = tid; i < 2048; i += BLOCK) hist[i] = 0;
        __syncthreads();
        for (int t = tid; t < ntok; t += BLOCK) {
            const float v = disp[(size_t)t * NE + e];
            if (v > 0.f) atomicAdd(&hist[__float_as_uint(v) >> 20], 1);
        }
        __syncthreads();
        suffix_scan256(hist, 2048);
        if (tid == 0) s_best = -1;
        __syncthreads();
        for (int i = tid; i < 2048; i += BLOCK)
            if (hist[i] >= cap) atomicMax(&s_best, i);
        __syncthreads();
        const int b1 = s_best;
        if (b1 < 0) { __syncthreads(); continue; }
        const int A1 = (b1 + 1 < 2048) ? hist[b1 + 1] : 0;
        const int cap2 = cap - A1;
        __syncthreads();

        // level 2: among bits>>20 == b1: bin = (bits >> 9) & 0x7FF
        for (int i = tid; i < 2048; i += BLOCK) hist[i] = 0;
        __syncthreads();
        for (int t = tid; t < ntok; t += BLOCK) {
            const float v = disp[(size_t)t * NE + e];
            if (v > 0.f) {
                const unsigned b = __float_as_uint(v);
                if ((int)(b >> 20) == b1) atomicAdd(&hist[(b >> 9) & 0x7FF], 1);
            }
        }
        __syncthreads();
        suffix_scan256(hist, 2048);
        if (tid == 0) s_best = -1;
        __syncthreads();
        for (int i = tid; i < 2048; i += BLOCK)
            if (hist[i] >= cap2) atomicMax(&s_best, i);
        __syncthreads();
        const int b2 = s_best;
        const int A2 = (b2 + 1 < 2048) ? hist[b2 + 1] : 0;
        const int cap3 = cap2 - A2;
        const unsigned key = ((unsigned)b1 << 11) | (unsigned)b2;   // == bits >> 9
        __syncthreads();

        // level 3: among bits>>9 == key: bin = bits & 0x1FF
        for (int i = tid; i < 512; i += BLOCK) hist[i] = 0;
        __syncthreads();
        for (int t = tid; t < ntok; t += BLOCK) {
            const float v = disp[(size_t)t * NE + e];
            if (v > 0.f) {
                const unsigned b = __float_as_uint(v);
                if ((b >> 9) == key) atomicAdd(&hist[b & 0x1FF], 1);
            }
        }
        __syncthreads();
        suffix_scan256(hist, 512);
        if (tid == 0) s_best = -1;
        __syncthreads();
        for (int i = tid; i < 512; i += BLOCK)
            if (hist[i] >= cap3) atomicMax(&s_best, i);
        __syncthreads();
        const int b3 = s_best;
        const int A3 = (b3 + 1 < 512) ? hist[b3 + 1] : 0;
        const int keep_eq = cap3 - A3;            // ==threshold entries that survive
        const unsigned thr = (key << 9) | (unsigned)b3;
        __syncthreads();

        // apply: zero below threshold; collect exact ties (reuse hist as buffer)
        int* s_ties = hist;
        if (tid == 0) s_tiecnt = 0;
        __syncthreads();
        for (int t = tid; t < ntok; t += BLOCK) {
            const size_t o = (size_t)t * NE + e;
            const float v = disp[o];
            if (v > 0.f) {
                const unsigned b = __float_as_uint(v);
                if (b < thr) {
                    disp[o] = 0.f;
                } else if (b == thr) {
                    const int p = atomicAdd(&s_tiecnt, 1);
                    if (p < 2048) s_ties[p] = t;
                }
            }
        }
        __syncthreads();
        const int tc = (s_tiecnt < 2048) ? s_tiecnt : 2048;
        if (s_tiecnt > keep_eq) {
            // keep the keep_eq ties with smallest token index (jax top_k order)
            for (int i = tid; i < tc; i += BLOCK) {
                const int ti = s_ties[i];
                int rank = 0;
                for (int j = 0; j < tc; j++) rank += (s_ties[j] < ti);
                if (rank >= keep_eq) disp[(size_t)ti * NE + e] = 0.f;
            }
        }
        __syncthreads();
    }
}

extern "C" void kernel_launch(void* const* d_in, const int* in_sizes, int n_in,
                              void* d_out, int out_size)
{
    const float* hs = (const float*)d_in[0];
    const float* rw = (const float*)d_in[1];
    int hsize = in_sizes[0];
    if (n_in >= 2 && in_sizes[0] < in_sizes[1]) {  // defensive: pick the big tensor as hidden
        hs = (const float*)d_in[1];
        rw = (const float*)d_in[0];
        hsize = in_sizes[1];
    }
    const int ntok = hsize / HDIM;

    float* out   = (float*)d_out;
    float* disp  = out;                          // [N, E]
    float* loss  = out + (size_t)ntok * NE;      // scalar
    float* probs = loss + 1;                     // [N, E]

    route_fused<<<GRID, BLOCK>>>(hs, rw, disp, probs, loss, ntok);
}